// round 8
// baseline (speedup 1.0000x reference)
#include <cuda_runtime.h>
#include <cstdint>

#define D        64
#define H        64
#define KTOT     129
#define NKSTEP   17              // K padded to 136
#define TPB      128
#define NW       4               // warps per CTA

#define XSTR     140             // words/row; 560 B row stride (16B aligned, conflict-free)
#define BSTR     140

// dynamic smem layout (bytes)
#define SM_X      0
#define SM_XBUF   (32 * XSTR * 4)                 // 17920 B per 32-row buffer
#define SM_X_SZ   (NW * 2 * SM_XBUF)              // 143360
#define SM_B      (SM_X + SM_X_SZ)
#define SM_B_SZ   (H * BSTR * 4)                  // 35840
#define SM_B1     (SM_B + SM_B_SZ)
#define SM_W2     (SM_B1 + 256)
#define SM_B2     (SM_W2 + 256)
#define SM_TOTAL  (SM_B2 + 16)                    // ~179.7 KB -> 1 CTA/SM

__device__ __align__(16) float g_Bimg[H * BSTR];  // W1^T padded, [n][k]

__global__ void prep_kernel(const float* __restrict__ W1) {
    for (int i = threadIdx.x; i < H * BSTR; i += blockDim.x) {
        int n = i / BSTR, k = i % BSTR;
        g_Bimg[i] = (k < KTOT) ? W1[k * H + n] : 0.0f;
    }
}

__device__ __forceinline__ uint32_t smem_u32(const void* p) {
    uint32_t a;
    asm("{ .reg .u64 t; cvta.to.shared.u64 t, %1; cvt.u32.u64 %0, t; }" : "=r"(a) : "l"(p));
    return a;
}
__device__ __forceinline__ void cp16(uint32_t saddr, const void* gaddr) {
    asm volatile("cp.async.cg.shared.global [%0], [%1], 16;" :: "r"(saddr), "l"(gaddr));
}
#define CP_COMMIT() asm volatile("cp.async.commit_group;" ::: "memory")
#define CP_WAIT1()  asm volatile("cp.async.wait_group 1;" ::: "memory")

__device__ __forceinline__ void ldsm_x4(uint32_t& r0, uint32_t& r1, uint32_t& r2, uint32_t& r3,
                                        uint32_t addr) {
    asm volatile("ldmatrix.sync.aligned.m8n8.x4.shared.b16 {%0,%1,%2,%3}, [%4];"
                 : "=r"(r0), "=r"(r1), "=r"(r2), "=r"(r3) : "r"(addr));
}
__device__ __forceinline__ void mma_tf32(float c[4],
                                         uint32_t a0, uint32_t a1, uint32_t a2, uint32_t a3,
                                         uint32_t b0, uint32_t b1) {
    asm volatile(
        "mma.sync.aligned.m16n8k8.row.col.f32.tf32.tf32.f32 "
        "{%0,%1,%2,%3}, {%4,%5,%6,%7}, {%8,%9}, {%0,%1,%2,%3};"
        : "+f"(c[0]), "+f"(c[1]), "+f"(c[2]), "+f"(c[3])
        : "r"(a0), "r"(a1), "r"(a2), "r"(a3), "r"(b0), "r"(b1));
}

__global__ __launch_bounds__(TPB)
void edge_mlp_pers_kernel(const float* __restrict__ hc,
                          const float* __restrict__ hp,
                          const int*   __restrict__ src,
                          const int*   __restrict__ dst,
                          const float* __restrict__ b1,
                          const float* __restrict__ W2,
                          const float* __restrict__ b2,
                          float*       __restrict__ out,
                          int E, int ns)
{
    extern __shared__ char smem[];
    const uint32_t smem_base = smem_u32(smem);
    float* sB1 = (float*)(smem + SM_B1);
    float* sW2 = (float*)(smem + SM_W2);
    float* sB2 = (float*)(smem + SM_B2);

    const int tid    = threadIdx.x;
    const int wid    = tid >> 5;
    const int lane   = tid & 31;
    const int wglob  = blockIdx.x * NW + wid;
    const int twarps = gridDim.x * NW;

    const int lane16  = lane & 15;
    const bool isHead = lane < 16;
    const uint32_t xbuf0 = smem_base + SM_X + (uint32_t)(wid * 2) * SM_XBUF;
    const uint32_t xbuf1 = xbuf0 + SM_XBUF;
    const uint32_t gcol4 = (uint32_t)(((isHead ? 0 : D) + lane16 * 4) * 4);

    // ---- index load for stage 0 (latency overlapped by B staging) ----
    const long long base0 = (long long)wglob * 32;
    {
        long long bb = base0 + lane;
        int ecl = (bb < E) ? (int)bb : (E - 1);
        // first-stage indices loaded below into sv/tv
        (void)ecl;
    }
    int sv, tv;
    {
        long long bb = base0 + lane;
        int ecl = (bb < E) ? (int)bb : (E - 1);
        sv = src[ecl]; tv = dst[ecl];
    }

    // ---- B / bias staging via cp.async (its own group) ----
    {
        const char* gB = (const char*)g_Bimg;
        uint32_t dB = smem_base + SM_B;
        #pragma unroll
        for (int i = 0; i < 18; ++i) {
            int c = i * TPB + tid;
            if (c < (H * BSTR) / 4) cp16(dB + c * 16u, gB + c * 16);
        }
    }
    CP_COMMIT();                       // group: B
    if (tid < H) { sB1[tid] = b1[tid]; sW2[tid] = W2[tid]; }
    if (tid == 0) sB2[0] = b2[0];

    // ---- gather stage 0 into buf0 ----
    #pragma unroll 8
    for (int el = 0; el < 32; ++el) {
        int si = __shfl_sync(0xffffffffu, sv, el);
        int ti = __shfl_sync(0xffffffffu, tv, el);
        const float* g = isHead ? hc + (size_t)si * D + lane16 * 4
                                : hp + (size_t)ti * D + lane16 * 4;
        cp16(xbuf0 + (uint32_t)el * (XSTR * 4u) + gcol4, g);
    }
    CP_COMMIT();                       // group: gather0

    // ---- index prefetch for stage 1 ----
    {
        long long bb = base0 + (long long)twarps * 32 + lane;
        int ecl = (bb < E) ? (int)bb : (E - 1);
        sv = src[ecl]; tv = dst[ecl];
    }

    CP_WAIT1();                        // B done (gather0 may be pending)
    __syncthreads();                   // B visible CTA-wide; last CTA barrier

    // ---- precomputed ldmatrix addresses ----
    const int j = lane >> 3;
    const int r = lane & 7;
    const uint32_t aoff = (uint32_t)((r + (j & 1) * 8) * XSTR) * 4u + (uint32_t)(j >> 1) * 16u;
    const uint32_t aA0_b0 = xbuf0 + aoff;
    const uint32_t aA0_b1 = xbuf1 + aoff;
    uint32_t aB[4];
    #pragma unroll
    for (int p = 0; p < 4; ++p)
        aB[p] = smem_base + SM_B
              + (uint32_t)((p * 16 + r + (j >> 1) * 8) * BSTR) * 4u
              + (uint32_t)(j & 1) * 16u;

    const int qrow  = lane >> 2;
    const int qlane = lane & 3;
    const float bias2v = sB2[0];

    // =================== persistent per-warp pipeline ===================
    for (int s = 0; s < ns; ++s) {
        const uint32_t bufC = (s & 1) ? xbuf1 : xbuf0;      // compute buffer
        const uint32_t bufN = (s & 1) ? xbuf0 : xbuf1;      // prefetch target

        // ---- issue gather for stage s+1 (indices already in sv/tv) ----
        #pragma unroll 8
        for (int el = 0; el < 32; ++el) {
            int si = __shfl_sync(0xffffffffu, sv, el);
            int ti = __shfl_sync(0xffffffffu, tv, el);
            const float* g = isHead ? hc + (size_t)si * D + lane16 * 4
                                    : hp + (size_t)ti * D + lane16 * 4;
            cp16(bufN + (uint32_t)el * (XSTR * 4u) + gcol4, g);
        }
        CP_COMMIT();

        // ---- prefetch indices for stage s+2 (latency hidden by MMA below) ----
        {
            long long bb = base0 + (long long)(s + 2) * twarps * 32 + lane;
            int ecl = (bb < E) ? (int)bb : (E - 1);
            sv = src[ecl]; tv = dst[ecl];
        }

        CP_WAIT1();                    // gather s complete
        __syncwarp();

        // ---- cosine: lane owns row lane of compute buffer ----
        {
            float* row = (float*)(smem + (bufC - smem_base)) + lane * XSTR;
            float nh = 0.f, nt = 0.f, dp = 0.f;
            #pragma unroll
            for (int i = 0; i < D; i += 4) {
                float4 h = *(const float4*)(row + i);
                float4 t = *(const float4*)(row + D + i);
                nh = fmaf(h.x, h.x, nh); nh = fmaf(h.y, h.y, nh);
                nh = fmaf(h.z, h.z, nh); nh = fmaf(h.w, h.w, nh);
                nt = fmaf(t.x, t.x, nt); nt = fmaf(t.y, t.y, nt);
                nt = fmaf(t.z, t.z, nt); nt = fmaf(t.w, t.w, nt);
                dp = fmaf(h.x, t.x, dp); dp = fmaf(h.y, t.y, dp);
                dp = fmaf(h.z, t.z, dp); dp = fmaf(h.w, t.w, dp);
            }
            float nhs = sqrtf(nh), nts = sqrtf(nt);
            float invh = 1.0f / fmaxf(nhs, 1e-12f);
            float invt = 1.0f / fmaxf(nts, 1e-12f);
            float hnn = nhs * invh, tnn = nts * invt;
            float cosv = (dp * invh * invt) / fmaxf(hnn * tnn, 1e-8f);
            *(float4*)(row + 128) = make_float4(cosv, 0.f, 0.f, 0.f);
            *(float4*)(row + 132) = make_float4(0.f, 0.f, 0.f, 0.f);
            *(float4*)(row + 136) = make_float4(0.f, 0.f, 0.f, 0.f);
        }
        __syncwarp();

        // ---- MMA mainloop ----
        const uint32_t aA0 = (s & 1) ? aA0_b1 : aA0_b0;
        const uint32_t aA1 = aA0 + 16u * XSTR * 4u;

        float acc[2][8][4];
        #pragma unroll
        for (int mt = 0; mt < 2; ++mt)
            #pragma unroll
            for (int nt = 0; nt < 8; ++nt)
                #pragma unroll
                for (int c = 0; c < 4; ++c) acc[mt][nt][c] = 0.f;

        #pragma unroll
        for (int ks = 0; ks < NKSTEP; ++ks) {
            const uint32_t ko = (uint32_t)ks * 32u;
            uint32_t a0[4], a1[4];
            ldsm_x4(a0[0], a0[1], a0[2], a0[3], aA0 + ko);
            ldsm_x4(a1[0], a1[1], a1[2], a1[3], aA1 + ko);
            uint32_t bf[8][2];
            #pragma unroll
            for (int p = 0; p < 4; ++p) {
                uint32_t r0, r1, r2, r3;
                ldsm_x4(r0, r1, r2, r3, aB[p] + ko);
                bf[2*p][0] = r0;   bf[2*p][1] = r1;
                bf[2*p+1][0] = r2; bf[2*p+1][1] = r3;
            }
            #pragma unroll
            for (int nt = 0; nt < 8; ++nt) {
                mma_tf32(acc[0][nt], a0[0], a0[1], a0[2], a0[3], bf[nt][0], bf[nt][1]);
                mma_tf32(acc[1][nt], a1[0], a1[1], a1[2], a1[3], bf[nt][0], bf[nt][1]);
            }
        }

        // ---- epilogue ----
        long long baseS = base0 + (long long)s * twarps * 32;
        #pragma unroll
        for (int mt = 0; mt < 2; ++mt) {
            #pragma unroll
            for (int rr = 0; rr < 2; ++rr) {
                float z = 0.f;
                #pragma unroll
                for (int nt = 0; nt < 8; ++nt) {
                    int n0 = nt * 8 + 2 * qlane;
                    float h0 = fmaxf(acc[mt][nt][2*rr]     + sB1[n0],     0.f);
                    float h1 = fmaxf(acc[mt][nt][2*rr + 1] + sB1[n0 + 1], 0.f);
                    z = fmaf(h0, sW2[n0], z);
                    z = fmaf(h1, sW2[n0 + 1], z);
                }
                z += __shfl_xor_sync(0xffffffffu, z, 1);
                z += __shfl_xor_sync(0xffffffffu, z, 2);
                if (qlane == 0) {
                    long long eo = baseS + mt * 16 + rr * 8 + qrow;
                    if (eo < E) {
                        float zz = z + bias2v;
                        out[eo] = 1.0f / (1.0f + expf(-zz));
                    }
                }
            }
        }
    }
}

extern "C" void kernel_launch(void* const* d_in, const int* in_sizes, int n_in,
                              void* d_out, int out_size)
{
    const float* hc  = (const float*)d_in[0];
    const float* hp  = (const float*)d_in[1];
    const int*   src = (const int*)  d_in[2];
    const int*   dst = (const int*)  d_in[3];
    const float* W1  = (const float*)d_in[4];
    const float* b1  = (const float*)d_in[5];
    const float* W2  = (const float*)d_in[6];
    const float* b2  = (const float*)d_in[7];
    float* out = (float*)d_out;

    static int nsm = 0;
    if (!nsm) {
        cudaDeviceGetAttribute(&nsm, cudaDevAttrMultiProcessorCount, 0);
        cudaFuncSetAttribute(edge_mlp_pers_kernel,
                             cudaFuncAttributeMaxDynamicSharedMemorySize, SM_TOTAL);
    }

    int E = in_sizes[2];
    int twarps = nsm * NW;
    int ngroups = (E + 31) / 32;
    int ns = (ngroups + twarps - 1) / twarps;

    prep_kernel<<<1, 256>>>(W1);
    edge_mlp_pers_kernel<<<nsm, TPB, SM_TOTAL>>>(hc, hp, src, dst, b1, W2, b2, out, E, ns);
}

// round 9
// speedup vs baseline: 1.9104x; 1.9104x over previous
#include <cuda_runtime.h>
#include <cuda_fp16.h>
#include <cstdint>

#define D        64
#define H        64
#define KTOT     129
#define NKS      9               // K padded to 144, k16 per MMA
#define TPB      128
#define NW       4
#define TILE_M   128

#define NMAXROW  100000

#define XSTRH    152             // halfs per row; 304 B row stride (16B aligned, conflict-free)
#define BSTRH    152

// dynamic smem layout (bytes)
#define SM_X      0
#define SM_XW     (32 * XSTRH * 2)                // 9728 B per warp (32 rows)
#define SM_X_SZ   (NW * SM_XW)                    // 38912
#define SM_B      (SM_X + SM_X_SZ)
#define SM_B_SZ   (H * BSTRH * 2)                 // 19456
#define SM_B1     (SM_B + SM_B_SZ)                // 64 f32
#define SM_W2     (SM_B1 + 256)
#define SM_B2     (SM_W2 + 256)
#define SM_TOTAL  (SM_B2 + 16)                    // ~58.9 KB -> 3 CTAs/SM

__device__ __align__(16) __half g_hc_h[NMAXROW * D];
__device__ __align__(16) __half g_hp_h[NMAXROW * D];
__device__ __align__(16) __half g_Bimg[H * BSTRH];   // W1^T fp16 padded, [n][k]

__global__ void cvt_kernel(const float* __restrict__ src, __half* __restrict__ dst, int n4) {
    int i = blockIdx.x * blockDim.x + threadIdx.x;
    if (i < n4) {
        float4 v = ((const float4*)src)[i];
        __half2 a = __floats2half2_rn(v.x, v.y);
        __half2 b = __floats2half2_rn(v.z, v.w);
        ((__half2*)dst)[2 * i]     = a;
        ((__half2*)dst)[2 * i + 1] = b;
    }
}

__global__ void prepB_kernel(const float* __restrict__ W1) {
    for (int i = threadIdx.x; i < H * BSTRH; i += blockDim.x) {
        int n = i / BSTRH, k = i % BSTRH;
        g_Bimg[i] = __float2half_rn((k < KTOT) ? W1[k * H + n] : 0.0f);
    }
}

__device__ __forceinline__ uint32_t smem_u32(const void* p) {
    uint32_t a;
    asm("{ .reg .u64 t; cvta.to.shared.u64 t, %1; cvt.u32.u64 %0, t; }" : "=r"(a) : "l"(p));
    return a;
}
__device__ __forceinline__ void cp16(uint32_t saddr, const void* gaddr) {
    asm volatile("cp.async.cg.shared.global [%0], [%1], 16;" :: "r"(saddr), "l"(gaddr));
}
__device__ __forceinline__ void ldsm_x4(uint32_t& r0, uint32_t& r1, uint32_t& r2, uint32_t& r3,
                                        uint32_t addr) {
    asm volatile("ldmatrix.sync.aligned.m8n8.x4.shared.b16 {%0,%1,%2,%3}, [%4];"
                 : "=r"(r0), "=r"(r1), "=r"(r2), "=r"(r3) : "r"(addr));
}
__device__ __forceinline__ void mma_f16(float c[4],
                                        uint32_t a0, uint32_t a1, uint32_t a2, uint32_t a3,
                                        uint32_t b0, uint32_t b1) {
    asm volatile(
        "mma.sync.aligned.m16n8k16.row.col.f32.f16.f16.f32 "
        "{%0,%1,%2,%3}, {%4,%5,%6,%7}, {%8,%9}, {%0,%1,%2,%3};"
        : "+f"(c[0]), "+f"(c[1]), "+f"(c[2]), "+f"(c[3])
        : "r"(a0), "r"(a1), "r"(a2), "r"(a3), "r"(b0), "r"(b1));
}

__global__ __launch_bounds__(TPB, 3)
void edge_mlp_f16_kernel(const int*   __restrict__ src,
                         const int*   __restrict__ dst,
                         const float* __restrict__ b1,
                         const float* __restrict__ W2,
                         const float* __restrict__ b2,
                         float*       __restrict__ out,
                         int E)
{
    extern __shared__ char smem[];
    const uint32_t smem_base = smem_u32(smem);
    float* sB1 = (float*)(smem + SM_B1);
    float* sW2 = (float*)(smem + SM_W2);
    float* sB2 = (float*)(smem + SM_B2);

    const int tid  = threadIdx.x;
    const int wid  = tid >> 5;
    const int lane = tid & 31;
    const int e0   = blockIdx.x * TILE_M;

    // ---- edge indices (latency overlapped by B staging below) ----
    int e  = e0 + wid * 32 + lane;
    int ec = (e < E) ? e : (E - 1);
    int sv = src[ec];
    int tv = dst[ec];

    // ---- B / bias staging via cp.async ----
    {
        const char* gB = (const char*)g_Bimg;
        uint32_t dB = smem_base + SM_B;
        #pragma unroll
        for (int i = 0; i < 10; ++i) {
            int c = i * TPB + tid;
            if (c < SM_B_SZ / 16) cp16(dB + (uint32_t)c * 16u, gB + c * 16);
        }
    }
    if (tid < H) { sB1[tid] = b1[tid]; sW2[tid] = W2[tid]; }
    if (tid == 0) sB2[0] = b2[0];

    const uint32_t xw = smem_base + SM_X + (uint32_t)wid * SM_XW;

    // ---- zero pad cols 128..151 of own row (bytes 256..303) ----
    {
        uint32_t rowb = xw + (uint32_t)lane * (XSTRH * 2u);
        uint4 z = make_uint4(0, 0, 0, 0);
        *(uint4*)(smem + (rowb - smem_base) + 256) = z;
        *(uint4*)(smem + (rowb - smem_base) + 272) = z;
        *(uint4*)(smem + (rowb - smem_base) + 288) = z;
    }

    // ---- gather: fp16 rows, 16B chunks; 2 edges per iteration ----
    {
        const int el2   = lane >> 4;          // 0..1
        const int part  = (lane >> 3) & 1;    // 0=head 1=tail
        const int chunk = lane & 7;           // 16B chunk within 128B row
        #pragma unroll 8
        for (int i = 0; i < 16; ++i) {
            int ew = 2 * i + el2;
            int si = __shfl_sync(0xffffffffu, sv, ew);
            int ti = __shfl_sync(0xffffffffu, tv, ew);
            const __half* g = part ? g_hp_h + (size_t)ti * D + chunk * 8
                                   : g_hc_h + (size_t)si * D + chunk * 8;
            cp16(xw + (uint32_t)ew * (XSTRH * 2u) + (uint32_t)(part * 128 + chunk * 16), g);
        }
    }
    asm volatile("cp.async.commit_group;" ::: "memory");
    asm volatile("cp.async.wait_group 0;" ::: "memory");
    __syncthreads();

    // ---- cosine from fp16 row (thread owns row tid within its warp block) ----
    {
        const uint32_t* rw = (const uint32_t*)(smem + SM_X + wid * SM_XW + lane * (XSTRH * 2));
        float nh = 0.f, nt = 0.f, dp = 0.f;
        #pragma unroll
        for (int i = 0; i < 8; ++i) {           // head 128B = 8 uint4
            uint4 hq = ((const uint4*)rw)[i];
            uint4 tq = ((const uint4*)rw)[i + 8];
            const uint32_t hu[4] = {hq.x, hq.y, hq.z, hq.w};
            const uint32_t tu[4] = {tq.x, tq.y, tq.z, tq.w};
            #pragma unroll
            for (int q = 0; q < 4; ++q) {
                float2 h2 = __half22float2(*(const __half2*)&hu[q]);
                float2 t2 = __half22float2(*(const __half2*)&tu[q]);
                nh = fmaf(h2.x, h2.x, nh); nh = fmaf(h2.y, h2.y, nh);
                nt = fmaf(t2.x, t2.x, nt); nt = fmaf(t2.y, t2.y, nt);
                dp = fmaf(h2.x, t2.x, dp); dp = fmaf(h2.y, t2.y, dp);
            }
        }
        float nhs = sqrtf(nh), nts = sqrtf(nt);
        float invh = 1.0f / fmaxf(nhs, 1e-12f);
        float invt = 1.0f / fmaxf(nts, 1e-12f);
        float hnn = nhs * invh, tnn = nts * invt;
        float cosv = (dp * invh * invt) / fmaxf(hnn * tnn, 1e-8f);
        *(__half*)(smem + SM_X + wid * SM_XW + lane * (XSTRH * 2) + 256) = __float2half_rn(cosv);
    }
    __syncwarp();

    // ---- ldmatrix addresses ----
    const int j = lane >> 3;   // 0..3
    const int r = lane & 7;
    // A: m0 rows0-7 k0 | m1 rows8-15 k0 | m2 rows0-7 +16B | m3 rows8-15 +16B
    const uint32_t aA0 = xw + (uint32_t)(((j & 1) * 8 + r) * (XSTRH * 2)) + (uint32_t)(j >> 1) * 16u;
    const uint32_t aA1 = aA0 + 16u * (XSTRH * 2u);
    // B: per p covers n rows p*16..p*16+15, both 16B k-halves
    uint32_t aB[4];
    #pragma unroll
    for (int p = 0; p < 4; ++p)
        aB[p] = smem_base + SM_B
              + (uint32_t)((p * 16 + r + (j >> 1) * 8) * (BSTRH * 2))
              + (uint32_t)(j & 1) * 16u;

    float acc[2][8][4];
    #pragma unroll
    for (int mt = 0; mt < 2; ++mt)
        #pragma unroll
        for (int nt = 0; nt < 8; ++nt)
            #pragma unroll
            for (int c = 0; c < 4; ++c) acc[mt][nt][c] = 0.f;

    // ---- mainloop: 9 k16 steps ----
    #pragma unroll
    for (int ks = 0; ks < NKS; ++ks) {
        const uint32_t ko = (uint32_t)ks * 32u;   // 16 halfs = 32 B
        uint32_t a0[4], a1[4];
        ldsm_x4(a0[0], a0[1], a0[2], a0[3], aA0 + ko);
        ldsm_x4(a1[0], a1[1], a1[2], a1[3], aA1 + ko);
        uint32_t bf[8][2];
        #pragma unroll
        for (int p = 0; p < 4; ++p) {
            uint32_t r0, r1, r2, r3;
            ldsm_x4(r0, r1, r2, r3, aB[p] + ko);
            bf[2*p][0] = r0;   bf[2*p][1] = r1;
            bf[2*p+1][0] = r2; bf[2*p+1][1] = r3;
        }
        #pragma unroll
        for (int nt = 0; nt < 8; ++nt) {
            mma_f16(acc[0][nt], a0[0], a0[1], a0[2], a0[3], bf[nt][0], bf[nt][1]);
            mma_f16(acc[1][nt], a1[0], a1[1], a1[2], a1[3], bf[nt][0], bf[nt][1]);
        }
    }

    // ---- epilogue ----
    const int qrow  = lane >> 2;
    const int qlane = lane & 3;
    const float bias2v = sB2[0];
    #pragma unroll
    for (int mt = 0; mt < 2; ++mt) {
        #pragma unroll
        for (int rr = 0; rr < 2; ++rr) {
            float z = 0.f;
            #pragma unroll
            for (int nt = 0; nt < 8; ++nt) {
                int n0 = nt * 8 + 2 * qlane;
                float h0 = fmaxf(acc[mt][nt][2*rr]     + sB1[n0],     0.f);
                float h1 = fmaxf(acc[mt][nt][2*rr + 1] + sB1[n0 + 1], 0.f);
                z = fmaf(h0, sW2[n0], z);
                z = fmaf(h1, sW2[n0 + 1], z);
            }
            z += __shfl_xor_sync(0xffffffffu, z, 1);
            z += __shfl_xor_sync(0xffffffffu, z, 2);
            if (qlane == 0) {
                int eo = e0 + wid * 32 + mt * 16 + rr * 8 + qrow;
                if (eo < E) {
                    float zz = z + bias2v;
                    out[eo] = 1.0f / (1.0f + expf(-zz));
                }
            }
        }
    }
}

extern "C" void kernel_launch(void* const* d_in, const int* in_sizes, int n_in,
                              void* d_out, int out_size)
{
    const float* hc  = (const float*)d_in[0];
    const float* hp  = (const float*)d_in[1];
    const int*   src = (const int*)  d_in[2];
    const int*   dst = (const int*)  d_in[3];
    const float* W1  = (const float*)d_in[4];
    const float* b1  = (const float*)d_in[5];
    const float* W2  = (const float*)d_in[6];
    const float* b2  = (const float*)d_in[7];
    float* out = (float*)d_out;

    static __half* hc_h = nullptr;
    static __half* hp_h = nullptr;
    static int inited = 0;
    if (!inited) {
        cudaGetSymbolAddress((void**)&hc_h, g_hc_h);
        cudaGetSymbolAddress((void**)&hp_h, g_hp_h);
        cudaFuncSetAttribute(edge_mlp_f16_kernel,
                             cudaFuncAttributeMaxDynamicSharedMemorySize, SM_TOTAL);
        inited = 1;
    }

    int E  = in_sizes[2];
    int n4c = in_sizes[0] / 4;
    int n4p = in_sizes[1] / 4;

    cvt_kernel<<<(n4c + 255) / 256, 256>>>(hc, hc_h, n4c);
    cvt_kernel<<<(n4p + 255) / 256, 256>>>(hp, hp_h, n4p);
    prepB_kernel<<<1, 256>>>(W1);

    int blocks = (E + TILE_M - 1) / TILE_M;
    edge_mlp_f16_kernel<<<blocks, TPB, SM_TOTAL>>>(src, dst, b1, W2, b2, out, E);
}

// round 10
// speedup vs baseline: 2.5170x; 1.3175x over previous
#include <cuda_runtime.h>
#include <cuda_fp16.h>
#include <cstdint>

#define D        64
#define H        64
#define KTOT     129
#define NKS      9               // K padded to 144, k16 per MMA
#define TPB      128
#define NW       4
#define TILE_M   128
#define CTAS_PER_SM 3

#define NMAXROW  100000

#define XSTRH    152             // halfs/row; 304 B row stride
#define BSTRH    152

// dynamic smem layout (bytes)
#define SM_X      0
#define SM_XW     (32 * XSTRH * 2)                // 9728 B per warp (32 rows)
#define SM_X_SZ   (NW * SM_XW)                    // 38912
#define SM_B      (SM_X + SM_X_SZ)
#define SM_B_SZ   (H * BSTRH * 2)                 // 19456
#define SM_B1     (SM_B + SM_B_SZ)
#define SM_W2     (SM_B1 + 256)
#define SM_B2     (SM_W2 + 256)
#define SM_TOTAL  (SM_B2 + 16)                    // ~58.9 KB -> 3 CTAs/SM

__device__ __align__(16) __half g_hc_h[NMAXROW * D];
__device__ __align__(16) __half g_hp_h[NMAXROW * D];
__device__ __align__(16) __half g_Bimg[H * BSTRH];

__global__ void prep_all(const float* __restrict__ hc, const float* __restrict__ hp,
                         const float* __restrict__ W1, int n4c, int n4p) {
    int i = blockIdx.x * blockDim.x + threadIdx.x;
    if (i < n4c) {
        float4 v = ((const float4*)hc)[i];
        ((__half2*)g_hc_h)[2 * i]     = __floats2half2_rn(v.x, v.y);
        ((__half2*)g_hc_h)[2 * i + 1] = __floats2half2_rn(v.z, v.w);
    } else if (i < n4c + n4p) {
        int k = i - n4c;
        float4 v = ((const float4*)hp)[k];
        ((__half2*)g_hp_h)[2 * k]     = __floats2half2_rn(v.x, v.y);
        ((__half2*)g_hp_h)[2 * k + 1] = __floats2half2_rn(v.z, v.w);
    }
    if (i < H * BSTRH) {
        int n = i / BSTRH, k = i % BSTRH;
        g_Bimg[i] = __float2half_rn((k < KTOT) ? W1[k * H + n] : 0.0f);
    }
}

__device__ __forceinline__ uint32_t smem_u32(const void* p) {
    uint32_t a;
    asm("{ .reg .u64 t; cvta.to.shared.u64 t, %1; cvt.u32.u64 %0, t; }" : "=r"(a) : "l"(p));
    return a;
}
__device__ __forceinline__ void cp16(uint32_t saddr, const void* gaddr) {
    asm volatile("cp.async.cg.shared.global [%0], [%1], 16;" :: "r"(saddr), "l"(gaddr));
}
__device__ __forceinline__ void ldsm_x4(uint32_t& r0, uint32_t& r1, uint32_t& r2, uint32_t& r3,
                                        uint32_t addr) {
    asm volatile("ldmatrix.sync.aligned.m8n8.x4.shared.b16 {%0,%1,%2,%3}, [%4];"
                 : "=r"(r0), "=r"(r1), "=r"(r2), "=r"(r3) : "r"(addr));
}
__device__ __forceinline__ void mma_f16(float c[4],
                                        uint32_t a0, uint32_t a1, uint32_t a2, uint32_t a3,
                                        uint32_t b0, uint32_t b1) {
    asm volatile(
        "mma.sync.aligned.m16n8k16.row.col.f32.f16.f16.f32 "
        "{%0,%1,%2,%3}, {%4,%5,%6,%7}, {%8,%9}, {%0,%1,%2,%3};"
        : "+f"(c[0]), "+f"(c[1]), "+f"(c[2]), "+f"(c[3])
        : "r"(a0), "r"(a1), "r"(a2), "r"(a3), "r"(b0), "r"(b1));
}

__global__ __launch_bounds__(TPB, CTAS_PER_SM)
void edge_mlp_f16_kernel(const int*   __restrict__ src,
                         const int*   __restrict__ dst,
                         const float* __restrict__ b1,
                         const float* __restrict__ W2,
                         const float* __restrict__ b2,
                         float*       __restrict__ out,
                         int E, int ntiles)
{
    extern __shared__ char smem[];
    const uint32_t smem_base = smem_u32(smem);
    float* sB1 = (float*)(smem + SM_B1);
    float* sW2 = (float*)(smem + SM_W2);
    float* sB2 = (float*)(smem + SM_B2);

    const int tid   = threadIdx.x;
    const int wid   = tid >> 5;
    const int lane  = tid & 31;
    const int ngrid = gridDim.x;

    const uint32_t xw = smem_base + SM_X + (uint32_t)wid * SM_XW;

    // gather role constants
    const int el2   = lane >> 4;
    const int part  = (lane >> 3) & 1;
    const int chunk = lane & 7;

    // ---- stage-0 indices ----
    int tile0 = blockIdx.x;
    int e0 = tile0 * TILE_M + wid * 32;
    int ec = e0 + lane; if (ec >= E) ec = E - 1;
    int sv = src[ec], tv = dst[ec];

    // ---- B / bias staging (once) ----
    {
        const char* gB = (const char*)g_Bimg;
        uint32_t dB = smem_base + SM_B;
        #pragma unroll
        for (int i = 0; i < 10; ++i) {
            int c = i * TPB + tid;
            if (c < SM_B_SZ / 16) cp16(dB + (uint32_t)c * 16u, gB + c * 16);
        }
    }
    if (tid < H) { sB1[tid] = b1[tid]; sW2[tid] = W2[tid]; }
    if (tid == 0) sB2[0] = b2[0];

    // ---- zero pad cols 128..151 once (rows reused every stage) ----
    {
        uint32_t rowb = (uint32_t)(SM_X + wid * SM_XW + lane * (XSTRH * 2));
        uint4 z = make_uint4(0, 0, 0, 0);
        *(uint4*)(smem + rowb + 256) = z;
        *(uint4*)(smem + rowb + 272) = z;
        *(uint4*)(smem + rowb + 288) = z;
    }

    // ---- gather stage 0 ----
    #pragma unroll 8
    for (int i = 0; i < 16; ++i) {
        int ew = 2 * i + el2;
        int si = __shfl_sync(0xffffffffu, sv, ew);
        int ti = __shfl_sync(0xffffffffu, tv, ew);
        const __half* g = part ? g_hp_h + (size_t)ti * D + chunk * 8
                               : g_hc_h + (size_t)si * D + chunk * 8;
        cp16(xw + (uint32_t)ew * (XSTRH * 2u) + (uint32_t)(part * 128 + chunk * 16), g);
    }
    asm volatile("cp.async.commit_group;" ::: "memory");

    // ---- prefetch stage-1 indices ----
    {
        long long bb = (long long)(tile0 + ngrid) * TILE_M + wid * 32 + lane;
        int ecl = (bb < E) ? (int)bb : (E - 1);
        sv = src[ecl]; tv = dst[ecl];
    }

    asm volatile("cp.async.wait_group 0;" ::: "memory");
    __syncthreads();                 // B visible; the only CTA-wide barrier

    // ---- ldmatrix addresses ----
    const int j = lane >> 3;
    const int r = lane & 7;
    const uint32_t aA0 = xw + (uint32_t)(((j & 1) * 8 + r) * (XSTRH * 2)) + (uint32_t)(j >> 1) * 16u;
    const uint32_t aA1 = aA0 + 16u * (XSTRH * 2u);
    uint32_t aB[4];
    #pragma unroll
    for (int p = 0; p < 4; ++p)
        aB[p] = smem_base + SM_B
              + (uint32_t)((p * 16 + r + (j >> 1) * 8) * (BSTRH * 2))
              + (uint32_t)(j & 1) * 16u;

    const int qrow  = lane >> 2;
    const int qlane = lane & 3;
    const float bias2v = sB2[0];
    const uint32_t rowb = (uint32_t)(SM_X + wid * SM_XW + lane * (XSTRH * 2));

    // =================== stage loop ===================
    for (int tile = tile0; tile < ntiles; tile += ngrid) {
        // ---- cosine for current stage ----
        {
            const uint4* rw = (const uint4*)(smem + rowb);
            float nh = 0.f, nt = 0.f, dp = 0.f;
            #pragma unroll
            for (int i = 0; i < 8; ++i) {
                uint4 hq = rw[i];
                uint4 tq = rw[i + 8];
                const uint32_t hu[4] = {hq.x, hq.y, hq.z, hq.w};
                const uint32_t tu[4] = {tq.x, tq.y, tq.z, tq.w};
                #pragma unroll
                for (int q = 0; q < 4; ++q) {
                    float2 h2 = __half22float2(*(const __half2*)&hu[q]);
                    float2 t2 = __half22float2(*(const __half2*)&tu[q]);
                    nh = fmaf(h2.x, h2.x, nh); nh = fmaf(h2.y, h2.y, nh);
                    nt = fmaf(t2.x, t2.x, nt); nt = fmaf(t2.y, t2.y, nt);
                    dp = fmaf(h2.x, t2.x, dp); dp = fmaf(h2.y, t2.y, dp);
                }
            }
            float nhs = sqrtf(nh), nts = sqrtf(nt);
            float invh = 1.0f / fmaxf(nhs, 1e-12f);
            float invt = 1.0f / fmaxf(nts, 1e-12f);
            float hnn = nhs * invh, tnn = nts * invt;
            float cosv = (dp * invh * invt) / fmaxf(hnn * tnn, 1e-8f);
            *(__half*)(smem + rowb + 256) = __float2half_rn(cosv);
        }
        __syncwarp();

        // ---- MMA mainloop ----
        float acc[2][8][4];
        #pragma unroll
        for (int mt = 0; mt < 2; ++mt)
            #pragma unroll
            for (int nt = 0; nt < 8; ++nt)
                #pragma unroll
                for (int c = 0; c < 4; ++c) acc[mt][nt][c] = 0.f;

        #pragma unroll
        for (int ks = 0; ks < NKS; ++ks) {
            const uint32_t ko = (uint32_t)ks * 32u;
            uint32_t a0[4], a1[4];
            ldsm_x4(a0[0], a0[1], a0[2], a0[3], aA0 + ko);
            ldsm_x4(a1[0], a1[1], a1[2], a1[3], aA1 + ko);
            uint32_t bf[8][2];
            #pragma unroll
            for (int p = 0; p < 4; ++p) {
                uint32_t r0, r1, r2, r3;
                ldsm_x4(r0, r1, r2, r3, aB[p] + ko);
                bf[2*p][0] = r0;   bf[2*p][1] = r1;
                bf[2*p+1][0] = r2; bf[2*p+1][1] = r3;
            }
            #pragma unroll
            for (int nt = 0; nt < 8; ++nt) {
                mma_f16(acc[0][nt], a0[0], a0[1], a0[2], a0[3], bf[nt][0], bf[nt][1]);
                mma_f16(acc[1][nt], a1[0], a1[1], a1[2], a1[3], bf[nt][0], bf[nt][1]);
            }
        }
        __syncwarp();   // all LDSMs of this stage done -> X buffer reusable

        // ---- issue gather for next stage (indices already in sv/tv) ----
        const int tnext = tile + ngrid;
        if (tnext < ntiles) {
            #pragma unroll 8
            for (int i = 0; i < 16; ++i) {
                int ew = 2 * i + el2;
                int si = __shfl_sync(0xffffffffu, sv, ew);
                int ti = __shfl_sync(0xffffffffu, tv, ew);
                const __half* g = part ? g_hp_h + (size_t)ti * D + chunk * 8
                                       : g_hc_h + (size_t)si * D + chunk * 8;
                cp16(xw + (uint32_t)ew * (XSTRH * 2u) + (uint32_t)(part * 128 + chunk * 16), g);
            }
        }
        asm volatile("cp.async.commit_group;" ::: "memory");

        // ---- prefetch indices for stage after next ----
        {
            long long bb = (long long)(tile + 2 * ngrid) * TILE_M + wid * 32 + lane;
            int ecl = (bb >= 0 && bb < E) ? (int)bb : (E - 1);
            sv = src[ecl]; tv = dst[ecl];
        }

        // ---- epilogue (register-only; hides gather latency) ----
        {
            const int ebase = tile * TILE_M + wid * 32;
            #pragma unroll
            for (int mt = 0; mt < 2; ++mt) {
                #pragma unroll
                for (int rr = 0; rr < 2; ++rr) {
                    float z = 0.f;
                    #pragma unroll
                    for (int nt = 0; nt < 8; ++nt) {
                        int n0 = nt * 8 + 2 * qlane;
                        float h0 = fmaxf(acc[mt][nt][2*rr]     + sB1[n0],     0.f);
                        float h1 = fmaxf(acc[mt][nt][2*rr + 1] + sB1[n0 + 1], 0.f);
                        z = fmaf(h0, sW2[n0], z);
                        z = fmaf(h1, sW2[n0 + 1], z);
                    }
                    z += __shfl_xor_sync(0xffffffffu, z, 1);
                    z += __shfl_xor_sync(0xffffffffu, z, 2);
                    if (qlane == 0) {
                        int eo = ebase + mt * 16 + rr * 8 + qrow;
                        if (eo < E) {
                            float zz = z + bias2v;
                            out[eo] = 1.0f / (1.0f + expf(-zz));
                        }
                    }
                }
            }
        }

        asm volatile("cp.async.wait_group 0;" ::: "memory");
        __syncwarp();
    }
}

extern "C" void kernel_launch(void* const* d_in, const int* in_sizes, int n_in,
                              void* d_out, int out_size)
{
    const float* hc  = (const float*)d_in[0];
    const float* hp  = (const float*)d_in[1];
    const int*   src = (const int*)  d_in[2];
    const int*   dst = (const int*)  d_in[3];
    const float* W1  = (const float*)d_in[4];
    const float* b1  = (const float*)d_in[5];
    const float* W2  = (const float*)d_in[6];
    const float* b2  = (const float*)d_in[7];
    float* out = (float*)d_out;

    static int nsm = 0;
    if (!nsm) {
        cudaDeviceGetAttribute(&nsm, cudaDevAttrMultiProcessorCount, 0);
        cudaFuncSetAttribute(edge_mlp_f16_kernel,
                             cudaFuncAttributeMaxDynamicSharedMemorySize, SM_TOTAL);
    }

    int E   = in_sizes[2];
    int n4c = in_sizes[0] / 4;
    int n4p = in_sizes[1] / 4;
    int n4  = n4c + n4p;

    prep_all<<<(n4 + 255) / 256, 256>>>(hc, hp, W1, n4c, n4p);

    int ntiles = (E + TILE_M - 1) / TILE_M;
    int ngrid  = nsm * CTAS_PER_SM;
    if (ngrid > ntiles) ngrid = ntiles;
    edge_mlp_f16_kernel<<<ngrid, TPB, SM_TOTAL>>>(src, dst, b1, W2, b2, out, E, ntiles);
}

// round 11
// speedup vs baseline: 2.6860x; 1.0672x over previous
#include <cuda_runtime.h>
#include <cuda_fp16.h>
#include <cstdint>

#define D        64
#define H        64
#define KTOT     129             // 2D + 1 (cos)
#define NKS      9               // K=130 (incl. bias col) padded to 144
#define TPB      128
#define NW       4
#define TILE_M   128
#define CTAS_PER_SM 3

#define NMAXROW  100000

#define XSTRH    152             // halfs/row; 304 B row stride (ldmatrix conflict-free)
#define BSTRH    152

// dynamic smem layout (bytes)
#define SM_X      0
#define SM_XW     (32 * XSTRH * 2)                // 9728 B per warp (32 rows)
#define SM_X_SZ   (NW * SM_XW)                    // 38912
#define SM_B      (SM_X + SM_X_SZ)
#define SM_B_SZ   (H * BSTRH * 2)                 // 19456
#define SM_W2     (SM_B + SM_B_SZ)                // 64 f32
#define SM_B2     (SM_W2 + 256)
#define SM_TOTAL  (SM_B2 + 16)                    // ~58.7 KB -> 3 CTAs/SM

__device__ __align__(16) __half g_hc_h[NMAXROW * D];
__device__ __align__(16) __half g_hp_h[NMAXROW * D];
__device__ __align__(16) __half g_Bimg[H * BSTRH];

__global__ void prep_all(const float* __restrict__ hc, const float* __restrict__ hp,
                         const float* __restrict__ W1, const float* __restrict__ b1,
                         int n4c, int n4p) {
    int i = blockIdx.x * blockDim.x + threadIdx.x;
    if (i < n4c) {
        float4 v = ((const float4*)hc)[i];
        ((__half2*)g_hc_h)[2 * i]     = __floats2half2_rn(v.x, v.y);
        ((__half2*)g_hc_h)[2 * i + 1] = __floats2half2_rn(v.z, v.w);
    } else if (i < n4c + n4p) {
        int k = i - n4c;
        float4 v = ((const float4*)hp)[k];
        ((__half2*)g_hp_h)[2 * k]     = __floats2half2_rn(v.x, v.y);
        ((__half2*)g_hp_h)[2 * k + 1] = __floats2half2_rn(v.z, v.w);
    }
    if (i < H * BSTRH) {
        int n = i / BSTRH, k = i % BSTRH;
        float v = 0.0f;
        if (k < KTOT)       v = W1[k * H + n];   // k=128 is the cos row
        else if (k == KTOT) v = b1[n];           // k=129: bias row (X col 129 = 1.0)
        g_Bimg[i] = __float2half_rn(v);
    }
}

__device__ __forceinline__ uint32_t smem_u32(const void* p) {
    uint32_t a;
    asm("{ .reg .u64 t; cvta.to.shared.u64 t, %1; cvt.u32.u64 %0, t; }" : "=r"(a) : "l"(p));
    return a;
}
__device__ __forceinline__ void cp16(uint32_t saddr, const void* gaddr) {
    asm volatile("cp.async.cg.shared.global [%0], [%1], 16;" :: "r"(saddr), "l"(gaddr));
}
__device__ __forceinline__ void ldsm_x4(uint32_t& r0, uint32_t& r1, uint32_t& r2, uint32_t& r3,
                                        uint32_t addr) {
    asm volatile("ldmatrix.sync.aligned.m8n8.x4.shared.b16 {%0,%1,%2,%3}, [%4];"
                 : "=r"(r0), "=r"(r1), "=r"(r2), "=r"(r3) : "r"(addr));
}
__device__ __forceinline__ void mma_f16(float c[4],
                                        uint32_t a0, uint32_t a1, uint32_t a2, uint32_t a3,
                                        uint32_t b0, uint32_t b1) {
    asm volatile(
        "mma.sync.aligned.m16n8k16.row.col.f32.f16.f16.f32 "
        "{%0,%1,%2,%3}, {%4,%5,%6,%7}, {%8,%9}, {%0,%1,%2,%3};"
        : "+f"(c[0]), "+f"(c[1]), "+f"(c[2]), "+f"(c[3])
        : "r"(a0), "r"(a1), "r"(a2), "r"(a3), "r"(b0), "r"(b1));
}

__global__ __launch_bounds__(TPB, CTAS_PER_SM)
void edge_mlp_f16_kernel(const int*   __restrict__ src,
                         const int*   __restrict__ dst,
                         const float* __restrict__ W2,
                         const float* __restrict__ b2,
                         float*       __restrict__ out,
                         int E, int ntiles)
{
    extern __shared__ char smem[];
    const uint32_t smem_base = smem_u32(smem);
    float* sW2 = (float*)(smem + SM_W2);
    float* sB2 = (float*)(smem + SM_B2);

    const int tid   = threadIdx.x;
    const int wid   = tid >> 5;
    const int lane  = tid & 31;
    const int ngrid = gridDim.x;

    const uint32_t xw = smem_base + SM_X + (uint32_t)wid * SM_XW;

    // gather role constants
    const int el2   = lane >> 4;
    const int part  = (lane >> 3) & 1;
    const int chunk = lane & 7;

    // ---- stage-0 indices ----
    int tile0 = blockIdx.x;
    int ec = tile0 * TILE_M + wid * 32 + lane; if (ec >= E) ec = E - 1;
    int sv = src[ec], tv = dst[ec];

    // ---- B / W2 staging (once) ----
    {
        const char* gB = (const char*)g_Bimg;
        uint32_t dB = smem_base + SM_B;
        #pragma unroll
        for (int i = 0; i < 10; ++i) {
            int c = i * TPB + tid;
            if (c < SM_B_SZ / 16) cp16(dB + (uint32_t)c * 16u, gB + c * 16);
        }
    }
    if (tid < H) sW2[tid] = W2[tid];
    if (tid == 0) sB2[0] = b2[0];

    // ---- zero pad cols 128..151 once (bytes 256..303) ----
    {
        uint32_t rowb = (uint32_t)(SM_X + wid * SM_XW + lane * (XSTRH * 2));
        uint4 z = make_uint4(0, 0, 0, 0);
        *(uint4*)(smem + rowb + 256) = z;
        *(uint4*)(smem + rowb + 272) = z;
        *(uint4*)(smem + rowb + 288) = z;
    }

    // ---- gather stage 0 ----
    #pragma unroll 8
    for (int i = 0; i < 16; ++i) {
        int ew = 2 * i + el2;
        int si = __shfl_sync(0xffffffffu, sv, ew);
        int ti = __shfl_sync(0xffffffffu, tv, ew);
        const __half* g = part ? g_hp_h + (size_t)ti * D + chunk * 8
                               : g_hc_h + (size_t)si * D + chunk * 8;
        cp16(xw + (uint32_t)ew * (XSTRH * 2u) + (uint32_t)(part * 128 + chunk * 16), g);
    }
    asm volatile("cp.async.commit_group;" ::: "memory");

    // ---- prefetch stage-1 indices ----
    {
        long long bb = (long long)(tile0 + ngrid) * TILE_M + wid * 32 + lane;
        int ecl = (bb < E) ? (int)bb : (E - 1);
        sv = src[ecl]; tv = dst[ecl];
    }

    asm volatile("cp.async.wait_group 0;" ::: "memory");
    __syncthreads();                 // B visible; only CTA-wide barrier

    // ---- ldmatrix addresses ----
    const int j = lane >> 3;
    const int r = lane & 7;
    const uint32_t aA0 = xw + (uint32_t)(((j & 1) * 8 + r) * (XSTRH * 2)) + (uint32_t)(j >> 1) * 16u;
    const uint32_t aA1 = aA0 + 16u * (XSTRH * 2u);
    uint32_t aB[4];
    #pragma unroll
    for (int p = 0; p < 4; ++p)
        aB[p] = smem_base + SM_B
              + (uint32_t)((p * 16 + r + (j >> 1) * 8) * (BSTRH * 2))
              + (uint32_t)(j & 1) * 16u;

    const int qrow  = lane >> 2;
    const int qlane = lane & 3;
    const float bias2v = sB2[0];
    const uint32_t rowb = (uint32_t)(SM_X + wid * SM_XW + lane * (XSTRH * 2));

    // =================== stage loop ===================
    for (int tile = tile0; tile < ntiles; tile += ngrid) {
        // ---- cosine (fp16 HFMA2 accumulation) + (cos, 1.0) column store ----
        {
            const uint4* rw = (const uint4*)(smem + rowb);
            __half2 nh2 = __float2half2_rn(0.f);
            __half2 nt2 = __float2half2_rn(0.f);
            __half2 dp2 = __float2half2_rn(0.f);
            #pragma unroll
            for (int i = 0; i < 8; ++i) {
                uint4 hq = rw[i];
                uint4 tq = rw[i + 8];
                const uint32_t hu[4] = {hq.x, hq.y, hq.z, hq.w};
                const uint32_t tu[4] = {tq.x, tq.y, tq.z, tq.w};
                #pragma unroll
                for (int q = 0; q < 4; ++q) {
                    __half2 hh = *(const __half2*)&hu[q];
                    __half2 tt = *(const __half2*)&tu[q];
                    nh2 = __hfma2(hh, hh, nh2);
                    nt2 = __hfma2(tt, tt, nt2);
                    dp2 = __hfma2(hh, tt, dp2);
                }
            }
            float2 fnh = __half22float2(nh2);
            float2 fnt = __half22float2(nt2);
            float2 fdp = __half22float2(dp2);
            float nh = fnh.x + fnh.y, nt = fnt.x + fnt.y, dp = fdp.x + fdp.y;
            float nhs = sqrtf(nh), nts = sqrtf(nt);
            float invh = 1.0f / fmaxf(nhs, 1e-12f);
            float invt = 1.0f / fmaxf(nts, 1e-12f);
            float hnn = nhs * invh, tnn = nts * invt;
            float cosv = (dp * invh * invt) / fmaxf(hnn * tnn, 1e-8f);
            *(__half2*)(smem + rowb + 256) = __floats2half2_rn(cosv, 1.0f);
        }
        __syncwarp();

        // ---- MMA mainloop: 9 k16 steps ----
        float acc[2][8][4];
        #pragma unroll
        for (int mt = 0; mt < 2; ++mt)
            #pragma unroll
            for (int nt = 0; nt < 8; ++nt)
                #pragma unroll
                for (int c = 0; c < 4; ++c) acc[mt][nt][c] = 0.f;

        #pragma unroll
        for (int ks = 0; ks < NKS; ++ks) {
            const uint32_t ko = (uint32_t)ks * 32u;
            uint32_t a0[4], a1[4];
            ldsm_x4(a0[0], a0[1], a0[2], a0[3], aA0 + ko);
            ldsm_x4(a1[0], a1[1], a1[2], a1[3], aA1 + ko);
            uint32_t bf[8][2];
            #pragma unroll
            for (int p = 0; p < 4; ++p) {
                uint32_t r0, r1, r2, r3;
                ldsm_x4(r0, r1, r2, r3, aB[p] + ko);
                bf[2*p][0] = r0;   bf[2*p][1] = r1;
                bf[2*p+1][0] = r2; bf[2*p+1][1] = r3;
            }
            #pragma unroll
            for (int nt = 0; nt < 8; ++nt) {
                mma_f16(acc[0][nt], a0[0], a0[1], a0[2], a0[3], bf[nt][0], bf[nt][1]);
                mma_f16(acc[1][nt], a1[0], a1[1], a1[2], a1[3], bf[nt][0], bf[nt][1]);
            }
        }
        __syncwarp();   // all LDSMs done -> X buffer reusable

        // ---- issue gather for next stage ----
        const int tnext = tile + ngrid;
        if (tnext < ntiles) {
            #pragma unroll 8
            for (int i = 0; i < 16; ++i) {
                int ew = 2 * i + el2;
                int si = __shfl_sync(0xffffffffu, sv, ew);
                int ti = __shfl_sync(0xffffffffu, tv, ew);
                const __half* g = part ? g_hp_h + (size_t)ti * D + chunk * 8
                                       : g_hc_h + (size_t)si * D + chunk * 8;
                cp16(xw + (uint32_t)ew * (XSTRH * 2u) + (uint32_t)(part * 128 + chunk * 16), g);
            }
        }
        asm volatile("cp.async.commit_group;" ::: "memory");

        // ---- prefetch indices for stage after next ----
        {
            long long bb = (long long)(tile + 2 * ngrid) * TILE_M + wid * 32 + lane;
            int ecl = (bb >= 0 && bb < E) ? (int)bb : (E - 1);
            sv = src[ecl]; tv = dst[ecl];
        }

        // ---- epilogue: relu + W2 dot (bias/cos already in MMA) ----
        {
            const int ebase = tile * TILE_M + wid * 32;
            #pragma unroll
            for (int mt = 0; mt < 2; ++mt) {
                #pragma unroll
                for (int rr = 0; rr < 2; ++rr) {
                    float z = 0.f;
                    #pragma unroll
                    for (int nt = 0; nt < 8; ++nt) {
                        int n0 = nt * 8 + 2 * qlane;
                        z = fmaf(fmaxf(acc[mt][nt][2*rr],     0.f), sW2[n0],     z);
                        z = fmaf(fmaxf(acc[mt][nt][2*rr + 1], 0.f), sW2[n0 + 1], z);
                    }
                    z += __shfl_xor_sync(0xffffffffu, z, 1);
                    z += __shfl_xor_sync(0xffffffffu, z, 2);
                    if (qlane == 0) {
                        int eo = ebase + mt * 16 + rr * 8 + qrow;
                        if (eo < E) {
                            float zz = z + bias2v;
                            out[eo] = 1.0f / (1.0f + expf(-zz));
                        }
                    }
                }
            }
        }

        asm volatile("cp.async.wait_group 0;" ::: "memory");
        __syncwarp();
    }
}

extern "C" void kernel_launch(void* const* d_in, const int* in_sizes, int n_in,
                              void* d_out, int out_size)
{
    const float* hc  = (const float*)d_in[0];
    const float* hp  = (const float*)d_in[1];
    const int*   src = (const int*)  d_in[2];
    const int*   dst = (const int*)  d_in[3];
    const float* W1  = (const float*)d_in[4];
    const float* b1  = (const float*)d_in[5];
    const float* W2  = (const float*)d_in[6];
    const float* b2  = (const float*)d_in[7];
    float* out = (float*)d_out;

    static int nsm = 0;
    if (!nsm) {
        cudaDeviceGetAttribute(&nsm, cudaDevAttrMultiProcessorCount, 0);
        cudaFuncSetAttribute(edge_mlp_f16_kernel,
                             cudaFuncAttributeMaxDynamicSharedMemorySize, SM_TOTAL);
    }

    int E   = in_sizes[2];
    int n4c = in_sizes[0] / 4;
    int n4p = in_sizes[1] / 4;
    int n4  = n4c + n4p;

    prep_all<<<(n4 + 255) / 256, 256>>>(hc, hp, W1, b1, n4c, n4p);

    int ntiles = (E + TILE_M - 1) / TILE_M;
    int ngrid  = nsm * CTAS_PER_SM;
    if (ngrid > ntiles) ngrid = ntiles;
    edge_mlp_f16_kernel<<<ngrid, TPB, SM_TOTAL>>>(src, dst, W2, b2, out, E, ntiles);
}